// round 3
// baseline (speedup 1.0000x reference)
#include <cuda_runtime.h>
#include <math.h>

#define NN 8192
#define FD 128
#define HEPS 1e-7f
#define MAXT (1.0f - 1e-6f)

// Scratch (no allocations allowed)
__device__ float g_V[NN * FD];       // log0(h_add(exp0(log0(x)@embed), embed_bias))
__device__ float g_W[NN * 2 * FD];   // log0(concat(x, exp0(adj@V)))

__device__ __forceinline__ float wsum(float v) {
#pragma unroll
    for (int o = 16; o > 0; o >>= 1) v += __shfl_xor_sync(0xffffffffu, v, o);
    return v;
}

// Shared Mobius epilogue: T (pre-activation GEMM result) lives in acc[8][4],
// warp owns full rows. MODE 0: log0(h_add(exp0(T),b)); MODE 1: h_add(exp0(T),b)
template <int MODE>
__device__ __forceinline__ void mobius_epi(float acc[8][4], const float* __restrict__ bias,
                                           int br, int wid, int lane,
                                           float* __restrict__ out) {
    float4 bv = ((const float4*)bias)[lane];
    float y2 = wsum(bv.x * bv.x + bv.y * bv.y + bv.z * bv.z + bv.w * bv.w);
#pragma unroll
    for (int r = 0; r < 8; r++) {
        int row = br + wid * 8 + r;
        float t0 = acc[r][0], t1 = acc[r][1], t2 = acc[r][2], t3 = acc[r][3];
        float ss  = wsum(t0 * t0 + t1 * t1 + t2 * t2 + t3 * t3);
        float dtb = wsum(t0 * bv.x + t1 * bv.y + t2 * bv.z + t3 * bv.w);
        float n = fmaxf(sqrtf(ss), HEPS);
        float s = tanhf(n) / n;                       // exp0 scale
        float x2 = s * s * ss;
        float xy = s * dtb;
        float cnum = 1.f + 2.f * xy + y2;
        float cx = 1.f - x2;
        float inv = 1.f / fmaxf(1.f + 2.f * xy + x2 * y2, HEPS);
        float o0 = (cnum * s * t0 + cx * bv.x) * inv;
        float o1 = (cnum * s * t1 + cx * bv.y) * inv;
        float o2 = (cnum * s * t2 + cx * bv.z) * inv;
        float o3 = (cnum * s * t3 + cx * bv.w) * inv;
        if (MODE == 0) {
            float sso = wsum(o0 * o0 + o1 * o1 + o2 * o2 + o3 * o3);
            float no = fmaxf(sqrtf(sso), HEPS);
            float so = atanhf(fminf(no, MAXT)) / no;
            o0 *= so; o1 *= so; o2 *= so; o3 *= so;
        }
        ((float4*)(out + (size_t)row * FD))[lane] = make_float4(o0, o1, o2, o3);
    }
}

// ---------------------------------------------------------------------------
// GEMM1 fused with log map: V = log0(h_add(exp0(log0(x) @ embed), eb))
// Block 128 thr = 4 warps x 8 rows. Full 32x128 A tile in smem; row norms and
// log0 scaling applied in-smem, then FMA-bound inner loop (k unrolled x4,
// LDS.128 everywhere).
// ---------------------------------------------------------------------------
__global__ void k_gemm1(const float* __restrict__ X, const float* __restrict__ B,
                        const float* __restrict__ bias, float* __restrict__ out) {
    __shared__ float As[32][FD];     // 16KB
    __shared__ float Bs[32][FD];     // 16KB
    const int tid = threadIdx.x;
    const int lane = tid & 31;
    const int wid = tid >> 5;
    const int br = blockIdx.x * 32;

    // load full A tile (32 rows x 128)
#pragma unroll
    for (int i = 0; i < 8; i++) {
        int idx4 = tid + i * 128;            // float4 index
        int r = idx4 >> 5, c4 = idx4 & 31;
        ((float4*)As[r])[c4] = ((const float4*)(X + (size_t)(br + r) * FD))[c4];
    }
    __syncthreads();

    // log0 scaling: warp wid handles rows wid*8..wid*8+7
#pragma unroll
    for (int r = 0; r < 8; r++) {
        int row = wid * 8 + r;
        float4 v = ((float4*)As[row])[lane];
        float ss = wsum(v.x * v.x + v.y * v.y + v.z * v.z + v.w * v.w);
        float n = fmaxf(sqrtf(ss), HEPS);
        float s = atanhf(fminf(n, MAXT)) / n;
        ((float4*)As[row])[lane] = make_float4(v.x * s, v.y * s, v.z * s, v.w * s);
    }

    float acc[8][4];
#pragma unroll
    for (int r = 0; r < 8; r++)
#pragma unroll
        for (int c = 0; c < 4; c++) acc[r][c] = 0.f;

    for (int k0 = 0; k0 < FD; k0 += 32) {
        __syncthreads();
#pragma unroll
        for (int i = 0; i < 8; i++) {        // 32x128 B tile via float4
            int idx4 = tid + i * 128;
            int k = idx4 >> 5, c4 = idx4 & 31;
            ((float4*)Bs[k])[c4] = ((const float4*)(B + (size_t)(k0 + k) * FD))[c4];
        }
        __syncthreads();
#pragma unroll
        for (int k4 = 0; k4 < 8; k4++) {
            float4 b0 = ((float4*)Bs[k4 * 4 + 0])[lane];
            float4 b1 = ((float4*)Bs[k4 * 4 + 1])[lane];
            float4 b2 = ((float4*)Bs[k4 * 4 + 2])[lane];
            float4 b3 = ((float4*)Bs[k4 * 4 + 3])[lane];
#pragma unroll
            for (int r = 0; r < 8; r++) {
                float4 a = *(const float4*)&As[wid * 8 + r][k0 + k4 * 4];
                acc[r][0] += a.x * b0.x + a.y * b1.x + a.z * b2.x + a.w * b3.x;
                acc[r][1] += a.x * b0.y + a.y * b1.y + a.z * b2.y + a.w * b3.y;
                acc[r][2] += a.x * b0.z + a.y * b1.z + a.z * b2.z + a.w * b3.z;
                acc[r][3] += a.x * b0.w + a.y * b1.w + a.z * b2.w + a.w * b3.w;
            }
        }
    }
    mobius_epi<0>(acc, bias, br, wid, lane, out);
}

// ---------------------------------------------------------------------------
// GEMM2: out = h_add(exp0(W @ layer), lb), KD = 256. A in K-chunks of 32.
// ---------------------------------------------------------------------------
__global__ void k_gemm2(const float* __restrict__ A, const float* __restrict__ B,
                        const float* __restrict__ bias, float* __restrict__ out) {
    __shared__ float As[32][32];
    __shared__ float Bs[32][FD];
    const int tid = threadIdx.x;
    const int lane = tid & 31;
    const int wid = tid >> 5;
    const int br = blockIdx.x * 32;

    float acc[8][4];
#pragma unroll
    for (int r = 0; r < 8; r++)
#pragma unroll
        for (int c = 0; c < 4; c++) acc[r][c] = 0.f;

    for (int k0 = 0; k0 < 2 * FD; k0 += 32) {
        __syncthreads();
#pragma unroll
        for (int i = 0; i < 2; i++) {        // 32x32 A chunk via float4
            int idx4 = tid + i * 128;        // 256 float4s
            int r = idx4 >> 3, c4 = idx4 & 7;
            ((float4*)As[r])[c4] = ((const float4*)(A + (size_t)(br + r) * (2 * FD) + k0))[c4];
        }
#pragma unroll
        for (int i = 0; i < 8; i++) {        // 32x128 B tile via float4
            int idx4 = tid + i * 128;
            int k = idx4 >> 5, c4 = idx4 & 31;
            ((float4*)Bs[k])[c4] = ((const float4*)(B + (size_t)(k0 + k) * FD))[c4];
        }
        __syncthreads();
#pragma unroll
        for (int k4 = 0; k4 < 8; k4++) {
            float4 b0 = ((float4*)Bs[k4 * 4 + 0])[lane];
            float4 b1 = ((float4*)Bs[k4 * 4 + 1])[lane];
            float4 b2 = ((float4*)Bs[k4 * 4 + 2])[lane];
            float4 b3 = ((float4*)Bs[k4 * 4 + 3])[lane];
#pragma unroll
            for (int r = 0; r < 8; r++) {
                float4 a = ((float4*)As[wid * 8 + r])[k4];
                acc[r][0] += a.x * b0.x + a.y * b1.x + a.z * b2.x + a.w * b3.x;
                acc[r][1] += a.x * b0.y + a.y * b1.y + a.z * b2.y + a.w * b3.y;
                acc[r][2] += a.x * b0.z + a.y * b1.z + a.z * b2.z + a.w * b3.z;
                acc[r][3] += a.x * b0.w + a.y * b1.w + a.z * b2.w + a.w * b3.w;
            }
        }
    }
    mobius_epi<1>(acc, bias, br, wid, lane, out);
}

// ---------------------------------------------------------------------------
// SpMM + concat/log fusion: W = log0(concat(x, exp0(adj @ V)))
// One warp per output row. Streams the 32KB adj row via LDG.128 streaming
// (__ldcs keeps V resident in L2), one ballot per 128-element chunk.
// ---------------------------------------------------------------------------
__global__ void k_spmm_fused(const float* __restrict__ adj, const float* __restrict__ V,
                             const float* __restrict__ x, float* __restrict__ W) {
    int row = (blockIdx.x * blockDim.x + threadIdx.x) >> 5;
    int lane = threadIdx.x & 31;
    if (row >= NN) return;
    const float4* arow = (const float4*)(adj + (size_t)row * NN);
    float ax = 0.f, ay = 0.f, az = 0.f, aw = 0.f;
    for (int base4 = 0; base4 < NN / 4; base4 += 32) {
        float4 a = __ldcs(&arow[base4 + lane]);
        bool nz = (a.x != 0.f) | (a.y != 0.f) | (a.z != 0.f) | (a.w != 0.f);
        unsigned m = __ballot_sync(0xffffffffu, nz);
        while (m) {
            int src = __ffs(m) - 1;
            m &= m - 1;
            float c0 = __shfl_sync(0xffffffffu, a.x, src);
            float c1 = __shfl_sync(0xffffffffu, a.y, src);
            float c2 = __shfl_sync(0xffffffffu, a.z, src);
            float c3 = __shfl_sync(0xffffffffu, a.w, src);
            int col = (base4 + src) * 4;
            if (c0 != 0.f) {
                float4 v = ((const float4*)(V + (size_t)(col + 0) * FD))[lane];
                ax += c0 * v.x; ay += c0 * v.y; az += c0 * v.z; aw += c0 * v.w;
            }
            if (c1 != 0.f) {
                float4 v = ((const float4*)(V + (size_t)(col + 1) * FD))[lane];
                ax += c1 * v.x; ay += c1 * v.y; az += c1 * v.z; aw += c1 * v.w;
            }
            if (c2 != 0.f) {
                float4 v = ((const float4*)(V + (size_t)(col + 2) * FD))[lane];
                ax += c2 * v.x; ay += c2 * v.y; az += c2 * v.z; aw += c2 * v.w;
            }
            if (c3 != 0.f) {
                float4 v = ((const float4*)(V + (size_t)(col + 3) * FD))[lane];
                ax += c3 * v.x; ay += c3 * v.y; az += c3 * v.z; aw += c3 * v.w;
            }
        }
    }
    // fused epilogue: W = log0(concat(x, exp0(AV)))
    float ssa = wsum(ax * ax + ay * ay + az * az + aw * aw);
    float na = fmaxf(sqrtf(ssa), HEPS);
    float sa = tanhf(na) / na;                 // neigh = sa * AV
    float4 xv = ((const float4*)(x + (size_t)row * FD))[lane];
    float ssx = wsum(xv.x * xv.x + xv.y * xv.y + xv.z * xv.z + xv.w * xv.w);
    float tot = ssx + sa * sa * ssa;           // ||concat||^2
    float n = fmaxf(sqrtf(tot), HEPS);
    float s = atanhf(fminf(n, MAXT)) / n;
    float* wr = W + (size_t)row * 2 * FD;
    ((float4*)wr)[lane] = make_float4(s * xv.x, s * xv.y, s * xv.z, s * xv.w);
    float sb = s * sa;
    ((float4*)(wr + FD))[lane] = make_float4(sb * ax, sb * ay, sb * az, sb * aw);
}

// ---------------------------------------------------------------------------
extern "C" void kernel_launch(void* const* d_in, const int* in_sizes, int n_in,
                              void* d_out, int out_size) {
    const float* x     = (const float*)d_in[0];
    const float* adj   = (const float*)d_in[1];
    const float* embed = (const float*)d_in[2];
    const float* layer = (const float*)d_in[3];
    const float* eb    = (const float*)d_in[4];
    const float* lb    = (const float*)d_in[5];
    float* out = (float*)d_out;
    (void)in_sizes; (void)n_in; (void)out_size;

    float *pV, *pW;
    cudaGetSymbolAddress((void**)&pV, g_V);
    cudaGetSymbolAddress((void**)&pW, g_W);

    // 1. V = log0(h_add(exp0(log0(x) @ embed), eb))
    k_gemm1<<<NN / 32, 128>>>(x, embed, eb, pV);
    // 2. W = log0(concat(x, exp0(adj @ V)))
    k_spmm_fused<<<NN / 8, 256>>>(adj, pV, x, pW);
    // 3. out = h_add(exp0(W @ layer), lb)
    k_gemm2<<<NN / 32, 128>>>(pW, layer, lb, out);
}

// round 4
// speedup vs baseline: 1.5381x; 1.5381x over previous
#include <cuda_runtime.h>
#include <math.h>

#define NN 8192
#define FD 128
#define HEPS 1e-7f
#define MAXT (1.0f - 1e-6f)

// Scratch (no allocations allowed)
__device__ float g_V[NN * FD];       // log0(h_add(exp0(log0(x)@embed), embed_bias))
__device__ float g_W[NN * 2 * FD];   // log0(concat(x, exp0(adj@V)))

__device__ __forceinline__ float wsum(float v) {
#pragma unroll
    for (int o = 16; o > 0; o >>= 1) v += __shfl_xor_sync(0xffffffffu, v, o);
    return v;
}

// Mobius epilogue for 4 rows/warp. Warp owns full rows (lane -> 4 cols).
// MODE 0: log0(h_add(exp0(T),b)); MODE 1: h_add(exp0(T),b)
template <int MODE>
__device__ __forceinline__ void mobius_epi4(float acc[4][4], const float* __restrict__ bias,
                                            int br, int wid, int lane,
                                            float* __restrict__ out) {
    float4 bv = ((const float4*)bias)[lane];
    float y2 = wsum(bv.x * bv.x + bv.y * bv.y + bv.z * bv.z + bv.w * bv.w);
#pragma unroll
    for (int r = 0; r < 4; r++) {
        int row = br + wid * 4 + r;
        float t0 = acc[r][0], t1 = acc[r][1], t2 = acc[r][2], t3 = acc[r][3];
        float ss  = wsum(t0 * t0 + t1 * t1 + t2 * t2 + t3 * t3);
        float dtb = wsum(t0 * bv.x + t1 * bv.y + t2 * bv.z + t3 * bv.w);
        float n = fmaxf(sqrtf(ss), HEPS);
        float s = tanhf(n) / n;                       // exp0 scale
        float x2 = s * s * ss;
        float xy = s * dtb;
        float cnum = 1.f + 2.f * xy + y2;
        float cx = 1.f - x2;
        float inv = 1.f / fmaxf(1.f + 2.f * xy + x2 * y2, HEPS);
        float o0 = (cnum * s * t0 + cx * bv.x) * inv;
        float o1 = (cnum * s * t1 + cx * bv.y) * inv;
        float o2 = (cnum * s * t2 + cx * bv.z) * inv;
        float o3 = (cnum * s * t3 + cx * bv.w) * inv;
        if (MODE == 0) {
            float sso = wsum(o0 * o0 + o1 * o1 + o2 * o2 + o3 * o3);
            float no = fmaxf(sqrtf(sso), HEPS);
            float so = atanhf(fminf(no, MAXT)) / no;
            o0 *= so; o1 *= so; o2 *= so; o3 *= so;
        }
        ((float4*)(out + (size_t)row * FD))[lane] = make_float4(o0, o1, o2, o3);
    }
}

// ---------------------------------------------------------------------------
// GEMM1 fused with log map: V = log0(h_add(exp0(log0(x) @ embed), eb))
// Block 256 thr = 8 warps x 4 rows (BM=32). Full A tile in smem, log0 in-smem.
// ---------------------------------------------------------------------------
__global__ __launch_bounds__(256) void k_gemm1(
    const float* __restrict__ X, const float* __restrict__ B,
    const float* __restrict__ bias, float* __restrict__ out) {
    __shared__ float As[32][FD];
    __shared__ float Bs[32][FD];
    const int tid = threadIdx.x;
    const int lane = tid & 31;
    const int wid = tid >> 5;        // 0..7
    const int br = blockIdx.x * 32;

    // load full 32x128 A tile (1024 float4 / 256 threads = 4 iters)
#pragma unroll
    for (int i = 0; i < 4; i++) {
        int idx4 = tid + i * 256;
        int r = idx4 >> 5, c4 = idx4 & 31;
        ((float4*)As[r])[c4] = ((const float4*)(X + (size_t)(br + r) * FD))[c4];
    }
    __syncthreads();

    // log0 scaling: warp wid owns rows wid*4..wid*4+3 (reads own rows only)
#pragma unroll
    for (int r = 0; r < 4; r++) {
        int row = wid * 4 + r;
        float4 v = ((float4*)As[row])[lane];
        float ss = wsum(v.x * v.x + v.y * v.y + v.z * v.z + v.w * v.w);
        float n = fmaxf(sqrtf(ss), HEPS);
        float s = atanhf(fminf(n, MAXT)) / n;
        ((float4*)As[row])[lane] = make_float4(v.x * s, v.y * s, v.z * s, v.w * s);
    }

    float acc[4][4];
#pragma unroll
    for (int r = 0; r < 4; r++)
#pragma unroll
        for (int c = 0; c < 4; c++) acc[r][c] = 0.f;

    for (int k0 = 0; k0 < FD; k0 += 32) {
        __syncthreads();
#pragma unroll
        for (int i = 0; i < 4; i++) {
            int idx4 = tid + i * 256;
            int k = idx4 >> 5, c4 = idx4 & 31;
            ((float4*)Bs[k])[c4] = ((const float4*)(B + (size_t)(k0 + k) * FD))[c4];
        }
        __syncthreads();
#pragma unroll
        for (int k4 = 0; k4 < 8; k4++) {
            float4 b0 = ((float4*)Bs[k4 * 4 + 0])[lane];
            float4 b1 = ((float4*)Bs[k4 * 4 + 1])[lane];
            float4 b2 = ((float4*)Bs[k4 * 4 + 2])[lane];
            float4 b3 = ((float4*)Bs[k4 * 4 + 3])[lane];
#pragma unroll
            for (int r = 0; r < 4; r++) {
                float4 a = *(const float4*)&As[wid * 4 + r][k0 + k4 * 4];
                acc[r][0] += a.x * b0.x + a.y * b1.x + a.z * b2.x + a.w * b3.x;
                acc[r][1] += a.x * b0.y + a.y * b1.y + a.z * b2.y + a.w * b3.y;
                acc[r][2] += a.x * b0.z + a.y * b1.z + a.z * b2.z + a.w * b3.z;
                acc[r][3] += a.x * b0.w + a.y * b1.w + a.z * b2.w + a.w * b3.w;
            }
        }
    }
    mobius_epi4<0>(acc, bias, br, wid, lane, out);
}

// ---------------------------------------------------------------------------
// GEMM2: out = h_add(exp0(W @ layer), lb), KD = 256. Same 8-warp x 4-row shape.
// ---------------------------------------------------------------------------
__global__ __launch_bounds__(256) void k_gemm2(
    const float* __restrict__ A, const float* __restrict__ B,
    const float* __restrict__ bias, float* __restrict__ out) {
    __shared__ float As[32][32];
    __shared__ float Bs[32][FD];
    const int tid = threadIdx.x;
    const int lane = tid & 31;
    const int wid = tid >> 5;
    const int br = blockIdx.x * 32;

    float acc[4][4];
#pragma unroll
    for (int r = 0; r < 4; r++)
#pragma unroll
        for (int c = 0; c < 4; c++) acc[r][c] = 0.f;

    for (int k0 = 0; k0 < 2 * FD; k0 += 32) {
        __syncthreads();
        {   // 32x32 A chunk: 256 float4 / 256 threads = 1 iter
            int r = tid >> 3, c4 = tid & 7;
            ((float4*)As[r])[c4] =
                ((const float4*)(A + (size_t)(br + r) * (2 * FD) + k0))[c4];
        }
#pragma unroll
        for (int i = 0; i < 4; i++) {
            int idx4 = tid + i * 256;
            int k = idx4 >> 5, c4 = idx4 & 31;
            ((float4*)Bs[k])[c4] = ((const float4*)(B + (size_t)(k0 + k) * FD))[c4];
        }
        __syncthreads();
#pragma unroll
        for (int k4 = 0; k4 < 8; k4++) {
            float4 b0 = ((float4*)Bs[k4 * 4 + 0])[lane];
            float4 b1 = ((float4*)Bs[k4 * 4 + 1])[lane];
            float4 b2 = ((float4*)Bs[k4 * 4 + 2])[lane];
            float4 b3 = ((float4*)Bs[k4 * 4 + 3])[lane];
#pragma unroll
            for (int r = 0; r < 4; r++) {
                float4 a = ((float4*)As[wid * 4 + r])[k4];
                acc[r][0] += a.x * b0.x + a.y * b1.x + a.z * b2.x + a.w * b3.x;
                acc[r][1] += a.x * b0.y + a.y * b1.y + a.z * b2.y + a.w * b3.y;
                acc[r][2] += a.x * b0.z + a.y * b1.z + a.z * b2.z + a.w * b3.z;
                acc[r][3] += a.x * b0.w + a.y * b1.w + a.z * b2.w + a.w * b3.w;
            }
        }
    }
    mobius_epi4<1>(acc, bias, br, wid, lane, out);
}

// ---------------------------------------------------------------------------
// SpMM + concat/log fusion: W = log0(concat(x, exp0(adj @ V)))
// One warp per output row, R1-proven scalar-ballot inner loop, one-chunk
// software prefetch of the adj DRAM stream.
// ---------------------------------------------------------------------------
__global__ __launch_bounds__(256) void k_spmm_fused(
    const float* __restrict__ adj, const float* __restrict__ V,
    const float* __restrict__ x, float* __restrict__ W) {
    int row = (blockIdx.x * blockDim.x + threadIdx.x) >> 5;
    int lane = threadIdx.x & 31;
    if (row >= NN) return;
    const float* arow = adj + (size_t)row * NN;
    float ax = 0.f, ay = 0.f, az = 0.f, aw = 0.f;

    float cur[4];
#pragma unroll
    for (int q = 0; q < 4; q++) cur[q] = arow[q * 32 + lane];

    for (int base = 0; base < NN; base += 128) {
        float nxt[4] = {0.f, 0.f, 0.f, 0.f};
        int nb = base + 128;
        if (nb < NN) {
#pragma unroll
            for (int q = 0; q < 4; q++) nxt[q] = arow[nb + q * 32 + lane];
        }
#pragma unroll
        for (int q = 0; q < 4; q++) {
            unsigned m = __ballot_sync(0xffffffffu, cur[q] != 0.f);
            while (m) {
                int src = __ffs(m) - 1;
                m &= m - 1;
                float aj = __shfl_sync(0xffffffffu, cur[q], src);
                float4 v = ((const float4*)(V + (size_t)(base + q * 32 + src) * FD))[lane];
                ax += aj * v.x; ay += aj * v.y; az += aj * v.z; aw += aj * v.w;
            }
        }
#pragma unroll
        for (int q = 0; q < 4; q++) cur[q] = nxt[q];
    }

    // fused epilogue: W = log0(concat(x, exp0(AV)))
    float ssa = wsum(ax * ax + ay * ay + az * az + aw * aw);
    float na = fmaxf(sqrtf(ssa), HEPS);
    float sa = tanhf(na) / na;                 // neigh = sa * AV
    float4 xv = ((const float4*)(x + (size_t)row * FD))[lane];
    float ssx = wsum(xv.x * xv.x + xv.y * xv.y + xv.z * xv.z + xv.w * xv.w);
    float tot = ssx + sa * sa * ssa;           // ||concat||^2
    float n = fmaxf(sqrtf(tot), HEPS);
    float s = atanhf(fminf(n, MAXT)) / n;
    float* wr = W + (size_t)row * 2 * FD;
    ((float4*)wr)[lane] = make_float4(s * xv.x, s * xv.y, s * xv.z, s * xv.w);
    float sb = s * sa;
    ((float4*)(wr + FD))[lane] = make_float4(sb * ax, sb * ay, sb * az, sb * aw);
}

// ---------------------------------------------------------------------------
extern "C" void kernel_launch(void* const* d_in, const int* in_sizes, int n_in,
                              void* d_out, int out_size) {
    const float* x     = (const float*)d_in[0];
    const float* adj   = (const float*)d_in[1];
    const float* embed = (const float*)d_in[2];
    const float* layer = (const float*)d_in[3];
    const float* eb    = (const float*)d_in[4];
    const float* lb    = (const float*)d_in[5];
    float* out = (float*)d_out;
    (void)in_sizes; (void)n_in; (void)out_size;

    float *pV, *pW;
    cudaGetSymbolAddress((void**)&pV, g_V);
    cudaGetSymbolAddress((void**)&pW, g_W);

    // 1. V = log0(h_add(exp0(log0(x) @ embed), eb))
    k_gemm1<<<NN / 32, 256>>>(x, embed, eb, pV);
    // 2. W = log0(concat(x, exp0(adj @ V)))
    k_spmm_fused<<<NN / 8, 256>>>(adj, pV, x, pW);
    // 3. out = h_add(exp0(W @ layer), lb)
    k_gemm2<<<NN / 32, 256>>>(pW, layer, lb, out);
}